// round 2
// baseline (speedup 1.0000x reference)
#include <cuda_runtime.h>
#include <cuda_bf16.h>

#define NN 50000
#define EE 800000
#define SCAN_BLK 1024
#define NSCAN_BLKS ((NN + 1 + SCAN_BLK - 1) / SCAN_BLK)

// ---------------- scratch (static device memory; no allocs) ----------------
__device__ float g_hp[NN * 128];
__device__ float g_neigh[NN * 128];
__device__ float g_h1[NN * 64];
__device__ float g_h2[NN * 128];
__device__ int   g_rowptr[NN + 1];
__device__ int   g_cursor[NN];
__device__ int   g_src_sorted[EE];
__device__ float g_ew_sorted[EE];
__device__ int   g_partials[NSCAN_BLKS];

// ---------------- CSR build ----------------
__global__ void zero_counts_kernel() {
    int i = blockIdx.x * blockDim.x + threadIdx.x;
    if (i <= NN) g_rowptr[i] = 0;
}

__global__ void hist_kernel(const int* __restrict__ dst) {
    int i = blockIdx.x * blockDim.x + threadIdx.x;
    if (i < EE) atomicAdd(&g_rowptr[dst[i] + 1], 1);
}

__global__ void scan_chunk_kernel(int n) {
    __shared__ int sdata[SCAN_BLK];
    int tid = threadIdx.x;
    int i = blockIdx.x * SCAN_BLK + tid;
    int v = (i < n) ? g_rowptr[i] : 0;
    sdata[tid] = v;
    __syncthreads();
    for (int off = 1; off < SCAN_BLK; off <<= 1) {
        int t = (tid >= off) ? sdata[tid - off] : 0;
        __syncthreads();
        sdata[tid] += t;
        __syncthreads();
    }
    if (i < n) g_rowptr[i] = sdata[tid];
    if (tid == SCAN_BLK - 1) g_partials[blockIdx.x] = sdata[tid];
}

__global__ void scan_partials_kernel(int nb) {
    // tiny: single thread sequential scan of block partials
    for (int i = 1; i < nb; i++) g_partials[i] += g_partials[i - 1];
}

__global__ void scan_add_kernel(int n) {
    int i = blockIdx.x * SCAN_BLK + threadIdx.x;
    if (i < n) {
        int off = (blockIdx.x > 0) ? g_partials[blockIdx.x - 1] : 0;
        int val = g_rowptr[i] + off;
        g_rowptr[i] = val;
        if (i < NN) g_cursor[i] = val;
    }
}

__global__ void scatter_kernel(const int* __restrict__ src,
                               const int* __restrict__ dst,
                               const float* __restrict__ ew) {
    int e = blockIdx.x * blockDim.x + threadIdx.x;
    if (e < EE) {
        int p = atomicAdd(&g_cursor[dst[e]], 1);
        g_src_sorted[p] = src[e];
        g_ew_sorted[p]  = ew[e];
    }
}

// ---------------- neighbor max (warp per node, no atomics) ----------------
template <int DIN>
__global__ void neigh_max_kernel(const float* __restrict__ hp, float* __restrict__ out) {
    int warp = (blockIdx.x * blockDim.x + threadIdx.x) >> 5;
    int lane = threadIdx.x & 31;
    if (warp >= NN) return;
    int beg = g_rowptr[warp];
    int end = g_rowptr[warp + 1];
    if (DIN == 128) {
        float4 m = make_float4(0.f, 0.f, 0.f, 0.f);
        for (int e = beg; e < end; e++) {
            int s = g_src_sorted[e];
            float w = g_ew_sorted[e];
            float4 v = *(const float4*)&hp[s * 128 + lane * 4];
            m.x = fmaxf(m.x, v.x * w);
            m.y = fmaxf(m.y, v.y * w);
            m.z = fmaxf(m.z, v.z * w);
            m.w = fmaxf(m.w, v.w * w);
        }
        *(float4*)&out[warp * 128 + lane * 4] = m;
    } else {  // DIN == 64
        float2 m = make_float2(0.f, 0.f);
        for (int e = beg; e < end; e++) {
            int s = g_src_sorted[e];
            float w = g_ew_sorted[e];
            float2 v = *(const float2*)&hp[s * 64 + lane * 2];
            m.x = fmaxf(m.x, v.x * w);
            m.y = fmaxf(m.y, v.y * w);
        }
        *(float2*)&out[warp * 64 + lane * 2] = m;
    }
}

// ---------------- fused GEMM: C = relu(A1@W1 [+ A2@W2] + bias) ----------------
// BM=128, BN=64, BK=32, 256 threads, TM=8, TN=4
template <int K, int NOUT, bool DUAL>
__global__ __launch_bounds__(256) void gemm_relu_kernel(
    const float* __restrict__ A1, const float* __restrict__ W1,
    const float* __restrict__ A2, const float* __restrict__ W2,
    const float* __restrict__ bias, float* __restrict__ C, int M)
{
    constexpr int BM = 128, BN = 64, BK = 32;
    __shared__ float As[BK][BM + 4];   // stride 132 (16B-aligned rows)
    __shared__ float Bs[BK][BN + 4];   // stride 68

    int tid = threadIdx.x;
    int tx = tid & 15;        // 16 col-groups of 4
    int ty = tid >> 4;        // 16 row-groups of 8
    int m0 = blockIdx.x * BM;
    int n0 = blockIdx.y * BN;

    float acc[8][4];
#pragma unroll
    for (int i = 0; i < 8; i++)
#pragma unroll
        for (int j = 0; j < 4; j++) acc[i][j] = 0.f;

    const int npass = DUAL ? 2 : 1;
    for (int pass = 0; pass < npass; pass++) {
        const float* A = (pass == 0) ? A1 : A2;
        const float* W = (pass == 0) ? W1 : W2;
        for (int kt = 0; kt < K; kt += BK) {
            // load A tile: BM*BK = 4096 floats = 1024 float4, 4 per thread
#pragma unroll
            for (int it = 0; it < 4; it++) {
                int f  = tid + 256 * it;
                int m  = f >> 3;          // 8 float4 per row (BK=32)
                int c4 = f & 7;
                int gr = m0 + m;
                float4 v = make_float4(0.f, 0.f, 0.f, 0.f);
                if (gr < M) v = *(const float4*)&A[(long)gr * K + kt + c4 * 4];
                As[c4 * 4 + 0][m] = v.x;
                As[c4 * 4 + 1][m] = v.y;
                As[c4 * 4 + 2][m] = v.z;
                As[c4 * 4 + 3][m] = v.w;
            }
            // load W tile: BK*BN = 2048 floats = 512 float4, 2 per thread
#pragma unroll
            for (int it = 0; it < 2; it++) {
                int f  = tid + 256 * it;
                int kk = f >> 4;          // 16 float4 per row (BN=64)
                int c4 = f & 15;
                float4 v = *(const float4*)&W[(kt + kk) * NOUT + n0 + c4 * 4];
                *(float4*)&Bs[kk][c4 * 4] = v;
            }
            __syncthreads();
#pragma unroll
            for (int kk = 0; kk < BK; kk++) {
                float4 w  = *(const float4*)&Bs[kk][tx * 4];
                float4 a0 = *(const float4*)&As[kk][ty * 8];
                float4 a1 = *(const float4*)&As[kk][ty * 8 + 4];
                float a[8] = {a0.x, a0.y, a0.z, a0.w, a1.x, a1.y, a1.z, a1.w};
#pragma unroll
                for (int i = 0; i < 8; i++) {
                    acc[i][0] = fmaf(a[i], w.x, acc[i][0]);
                    acc[i][1] = fmaf(a[i], w.y, acc[i][1]);
                    acc[i][2] = fmaf(a[i], w.z, acc[i][2]);
                    acc[i][3] = fmaf(a[i], w.w, acc[i][3]);
                }
            }
            __syncthreads();
        }
    }

    float4 bv = *(const float4*)&bias[n0 + tx * 4];
#pragma unroll
    for (int i = 0; i < 8; i++) {
        int r = m0 + ty * 8 + i;
        if (r < M) {
            float4 o;
            o.x = fmaxf(acc[i][0] + bv.x, 0.f);
            o.y = fmaxf(acc[i][1] + bv.y, 0.f);
            o.z = fmaxf(acc[i][2] + bv.z, 0.f);
            o.w = fmaxf(acc[i][3] + bv.w, 0.f);
            *(float4*)&C[(long)r * NOUT + n0 + tx * 4] = o;
        }
    }
}

// ---------------- launch ----------------
static inline dim3 gemm_grid(int M, int NOUT) {
    return dim3((M + 127) / 128, NOUT / 64, 1);
}

extern "C" void kernel_launch(void* const* d_in, const int* in_sizes, int n_in,
                              void* d_out, int out_size) {
    const float* feat = (const float*)d_in[0];
    const int*   src  = (const int*)d_in[1];
    const int*   dst  = (const int*)d_in[2];
    const float* ew   = (const float*)d_in[3];
    const float* Wp1 = (const float*)d_in[4],  *bp1 = (const float*)d_in[5];
    const float* Ws1 = (const float*)d_in[6],  *Wn1 = (const float*)d_in[7],  *b1 = (const float*)d_in[8];
    const float* Wp2 = (const float*)d_in[9],  *bp2 = (const float*)d_in[10];
    const float* Ws2 = (const float*)d_in[11], *Wn2 = (const float*)d_in[12], *b2 = (const float*)d_in[13];
    const float* Wp3 = (const float*)d_in[14], *bp3 = (const float*)d_in[15];
    const float* Ws3 = (const float*)d_in[16], *Wn3 = (const float*)d_in[17], *b3 = (const float*)d_in[18];
    float* out = (float*)d_out;

    float *hp, *neigh, *h1, *h2;
    cudaGetSymbolAddress((void**)&hp, g_hp);
    cudaGetSymbolAddress((void**)&neigh, g_neigh);
    cudaGetSymbolAddress((void**)&h1, g_h1);
    cudaGetSymbolAddress((void**)&h2, g_h2);

    const int M = NN;

    // ---- CSR build (dst is the same for all 3 layers) ----
    zero_counts_kernel<<<(NN + 256) / 256, 256>>>();
    hist_kernel<<<(EE + 255) / 256, 256>>>(dst);
    scan_chunk_kernel<<<NSCAN_BLKS, SCAN_BLK>>>(NN + 1);
    scan_partials_kernel<<<1, 1>>>(NSCAN_BLKS);
    scan_add_kernel<<<NSCAN_BLKS, SCAN_BLK>>>(NN + 1);
    scatter_kernel<<<(EE + 255) / 256, 256>>>(src, dst, ew);

    dim3 nblk((NN * 32 + 255) / 256);

    // ---- Layer 1: 128 -> 64 ----
    gemm_relu_kernel<128, 128, false><<<gemm_grid(M, 128), 256>>>(feat, Wp1, nullptr, nullptr, bp1, hp, M);
    neigh_max_kernel<128><<<nblk, 256>>>(hp, neigh);
    gemm_relu_kernel<128, 64, true><<<gemm_grid(M, 64), 256>>>(feat, Ws1, neigh, Wn1, b1, h1, M);

    // ---- Layer 2: 64 -> 128 ----
    gemm_relu_kernel<64, 64, false><<<gemm_grid(M, 64), 256>>>(h1, Wp2, nullptr, nullptr, bp2, hp, M);
    neigh_max_kernel<64><<<nblk, 256>>>(hp, neigh);
    gemm_relu_kernel<64, 128, true><<<gemm_grid(M, 128), 256>>>(h1, Ws2, neigh, Wn2, b2, h2, M);

    // ---- Layer 3: 128 -> 128 ----
    gemm_relu_kernel<128, 128, false><<<gemm_grid(M, 128), 256>>>(h2, Wp3, nullptr, nullptr, bp3, hp, M);
    neigh_max_kernel<128><<<nblk, 256>>>(hp, neigh);
    gemm_relu_kernel<128, 128, true><<<gemm_grid(M, 128), 256>>>(h2, Ws3, neigh, Wn3, b3, out, M);
}

// round 5
// speedup vs baseline: 1.1347x; 1.1347x over previous
#include <cuda_runtime.h>
#include <cuda_bf16.h>
#include <cstdint>

#define NN 50000
#define EE 800000
#define SCAN_BLK 1024
#define NSCAN_BLKS ((NN + 1 + SCAN_BLK - 1) / SCAN_BLK)

// ---------------- scratch (static device memory; no allocs) ----------------
__device__ uint32_t g_feat_pk[NN * 128];
__device__ uint32_t g_hp_pk[NN * 128];
__device__ uint32_t g_neigh_pk[NN * 128];
__device__ uint32_t g_h1_pk[NN * 64];
__device__ uint32_t g_h2_pk[NN * 128];
__device__ uint32_t g_w_pk[102400];     // transposed split-bf16 weights, [Nout][K]
__device__ int   g_rowptr[NN + 1];
__device__ int   g_cursor[NN];
__device__ int   g_src_sorted[EE];
__device__ float g_ew_sorted[EE];
__device__ int   g_partials[NSCAN_BLKS];

// weight scratch offsets (uint32 elements), layout [Nout][K]
#define WOFF_P1 0        // 128x128
#define WOFF_S1 16384    // 64x128
#define WOFF_N1 24576    // 64x128
#define WOFF_P2 32768    // 64x64
#define WOFF_S2 36864    // 128x64
#define WOFF_N2 45056    // 128x64
#define WOFF_P3 53248    // 128x128
#define WOFF_S3 69632    // 128x128
#define WOFF_N3 86016    // 128x128

// ---------------- split-bf16 helpers ----------------
// packed u32: high 16 bits = bf16(x) ("hi"), low 16 bits = bf16(x - hi) ("lo")
__device__ __forceinline__ uint32_t pack_split(float x) {
    __nv_bfloat16 h = __float2bfloat16(x);
    float hf = __bfloat162float(h);
    __nv_bfloat16 l = __float2bfloat16(x - hf);
    return ((uint32_t)__bfloat16_as_ushort(h) << 16) | (uint32_t)__bfloat16_as_ushort(l);
}
__device__ __forceinline__ float unpack_split(uint32_t w) {
    float hf = __bfloat162float(__ushort_as_bfloat16((unsigned short)(w >> 16)));
    float lf = __bfloat162float(__ushort_as_bfloat16((unsigned short)(w & 0xFFFFu)));
    return hf + lf;
}

// ---------------- mma.sync m16n8k16 bf16 (baseline PTX, sm_80+) ----------------
__device__ __forceinline__ void mma16816(float* c, const uint32_t* a, uint32_t b0, uint32_t b1) {
    asm volatile(
        "mma.sync.aligned.m16n8k16.row.col.f32.bf16.bf16.f32 "
        "{%0,%1,%2,%3}, {%4,%5,%6,%7}, {%8,%9}, {%0,%1,%2,%3};"
        : "+f"(c[0]), "+f"(c[1]), "+f"(c[2]), "+f"(c[3])
        : "r"(a[0]), "r"(a[1]), "r"(a[2]), "r"(a[3]), "r"(b0), "r"(b1));
}
// extract bf16x2 planes from two packed u32 (elements k, k+1)
#define SEL_HI 0x7632u   // {pk0.hi16, pk1.hi16}
#define SEL_LO 0x5410u   // {pk0.lo16, pk1.lo16}

// ---------------- pack feat ----------------
__global__ void pack_feat_kernel(const float* __restrict__ f) {
    int i = blockIdx.x * blockDim.x + threadIdx.x;
    if (i < NN * 128) g_feat_pk[i] = pack_split(f[i]);
}

// ---------------- combined weight prep: transpose + split-pack all 9 weights ----------------
__global__ void wprep_all_kernel(
    const float* __restrict__ W0, const float* __restrict__ W1t, const float* __restrict__ W2t,
    const float* __restrict__ W3, const float* __restrict__ W4, const float* __restrict__ W5,
    const float* __restrict__ W6, const float* __restrict__ W7, const float* __restrict__ W8)
{
    const float* Ws[9] = {W0, W1t, W2t, W3, W4, W5, W6, W7, W8};
    const int off[9] = {WOFF_P1, WOFF_S1, WOFF_N1, WOFF_P2, WOFF_S2, WOFF_N2, WOFF_P3, WOFF_S3, WOFF_N3};
    const int Kd [9] = {128, 128, 128, 64, 64, 64, 128, 128, 128};
    const int Nd [9] = {128, 64, 64, 64, 128, 128, 128, 128, 128};
    int s = blockIdx.y;
    int sz = Kd[s] * Nd[s];
    int i = blockIdx.x * blockDim.x + threadIdx.x;
    if (i < sz) {
        int k = i / Nd[s], n = i % Nd[s];
        g_w_pk[off[s] + n * Kd[s] + k] = pack_split(Ws[s][k * Nd[s] + n]);
    }
}

// ---------------- CSR build ----------------
__global__ void zero_counts_kernel() {
    int i = blockIdx.x * blockDim.x + threadIdx.x;
    if (i <= NN) g_rowptr[i] = 0;
}
__global__ void hist_kernel(const int* __restrict__ dst) {
    int i = blockIdx.x * blockDim.x + threadIdx.x;
    if (i < EE) atomicAdd(&g_rowptr[dst[i] + 1], 1);
}
__global__ void scan_chunk_kernel(int n) {
    __shared__ int sdata[SCAN_BLK];
    int tid = threadIdx.x;
    int i = blockIdx.x * SCAN_BLK + tid;
    int v = (i < n) ? g_rowptr[i] : 0;
    sdata[tid] = v;
    __syncthreads();
    for (int off = 1; off < SCAN_BLK; off <<= 1) {
        int t = (tid >= off) ? sdata[tid - off] : 0;
        __syncthreads();
        sdata[tid] += t;
        __syncthreads();
    }
    if (i < n) g_rowptr[i] = sdata[tid];
    if (tid == SCAN_BLK - 1) g_partials[blockIdx.x] = sdata[tid];
}
__global__ void scan_partials_kernel(int nb) {
    __shared__ int sh[64];
    int t = threadIdx.x;
    sh[t] = (t < nb) ? g_partials[t] : 0;
    __syncthreads();
    for (int off = 1; off < 64; off <<= 1) {
        int x = (t >= off) ? sh[t - off] : 0;
        __syncthreads();
        sh[t] += x;
        __syncthreads();
    }
    if (t < nb) g_partials[t] = sh[t];
}
__global__ void scan_add_kernel(int n) {
    int i = blockIdx.x * SCAN_BLK + threadIdx.x;
    if (i < n) {
        int off = (blockIdx.x > 0) ? g_partials[blockIdx.x - 1] : 0;
        int val = g_rowptr[i] + off;
        g_rowptr[i] = val;
        if (i < NN) g_cursor[i] = val;
    }
}
__global__ void scatter_kernel(const int* __restrict__ src,
                               const int* __restrict__ dst,
                               const float* __restrict__ ew) {
    int e = blockIdx.x * blockDim.x + threadIdx.x;
    if (e < EE) {
        int p = atomicAdd(&g_cursor[dst[e]], 1);
        g_src_sorted[p] = src[e];
        g_ew_sorted[p]  = ew[e];
    }
}

// ---------------- neighbor max (packed in/out, warp per node, no atomics) ----------------
template <int DIN>
__global__ void neigh_max_pk(const uint32_t* __restrict__ hp, uint32_t* __restrict__ out) {
    int warp = (blockIdx.x * blockDim.x + threadIdx.x) >> 5;
    int lane = threadIdx.x & 31;
    if (warp >= NN) return;
    int beg = g_rowptr[warp];
    int end = g_rowptr[warp + 1];
    if (DIN == 128) {
        float m0 = 0.f, m1 = 0.f, m2 = 0.f, m3 = 0.f;
        for (int e = beg; e < end; e++) {
            int s = g_src_sorted[e];
            float w = g_ew_sorted[e];
            uint4 p = *(const uint4*)&hp[(size_t)s * 128 + lane * 4];
            m0 = fmaxf(m0, unpack_split(p.x) * w);
            m1 = fmaxf(m1, unpack_split(p.y) * w);
            m2 = fmaxf(m2, unpack_split(p.z) * w);
            m3 = fmaxf(m3, unpack_split(p.w) * w);
        }
        uint4 o;
        o.x = pack_split(m0); o.y = pack_split(m1);
        o.z = pack_split(m2); o.w = pack_split(m3);
        *(uint4*)&out[(size_t)warp * 128 + lane * 4] = o;
    } else {
        float m0 = 0.f, m1 = 0.f;
        for (int e = beg; e < end; e++) {
            int s = g_src_sorted[e];
            float w = g_ew_sorted[e];
            uint2 p = *(const uint2*)&hp[(size_t)s * 64 + lane * 2];
            m0 = fmaxf(m0, unpack_split(p.x) * w);
            m1 = fmaxf(m1, unpack_split(p.y) * w);
        }
        uint2 o;
        o.x = pack_split(m0); o.y = pack_split(m1);
        *(uint2*)&out[(size_t)warp * 64 + lane * 2] = o;
    }
}

// ---------------- HMMA GEMM: out = relu(A1@W1t [+ A2@W2t] + bias) ----------------
// CTA 256 threads (8 warps), tile 128 x 64. Warp tile 16 x 64 (8 x m16n8k16).
// Split-bf16 3-pass: hi*hi + hi*lo + lo*hi, fp32 register accumulators.
// A: [M][K] packed u32.  W: [Nout][K] packed u32 (row-major = B col-major for mma).
template <int K, bool DUAL, bool FINAL>
__global__ __launch_bounds__(256, 1) void mma_gemm(
    const uint32_t* __restrict__ A1, const uint32_t* __restrict__ W1,
    const uint32_t* __restrict__ A2, const uint32_t* __restrict__ W2,
    const float* __restrict__ bias, void* __restrict__ outp,
    int M, int NOUTtot)
{
    constexpr int SA = K + 4;                 // u32 stride (16B-aligned rows)
    extern __shared__ uint32_t smem[];
    uint32_t* sA = smem;                      // [128][SA]
    uint32_t* sB = smem + 128 * SA;           // [64][SA]

    int tid = threadIdx.x;
    int warp = tid >> 5, lane = tid & 31;
    int m0 = blockIdx.x * 128;
    int n0 = blockIdx.y * 64;

    int r  = lane >> 2;          // 0..7
    int kp = (lane & 3) * 2;     // 0,2,4,6
    int mrow = warp * 16 + r;    // warp's fragment row (within tile)

    float acc[8][4];
#pragma unroll
    for (int nt = 0; nt < 8; nt++)
#pragma unroll
        for (int j = 0; j < 4; j++) acc[nt][j] = 0.f;

    const int npass = DUAL ? 2 : 1;
    for (int phase = 0; phase < npass; phase++) {
        const uint32_t* A = (phase == 0) ? A1 : A2;
        const uint32_t* W = (phase == 0) ? W1 : W2;
        if (phase) __syncthreads();           // all reads of prev tiles done

        // fill A tile: 128 rows x K u32 (uint4 chunks)
        constexpr int AC4 = K / 4;
        for (int idx = tid; idx < 128 * AC4; idx += 256) {
            int row = idx / AC4, c4 = idx % AC4;
            uint4 v = make_uint4(0, 0, 0, 0);
            if (m0 + row < M) v = *(const uint4*)&A[(size_t)(m0 + row) * K + c4 * 4];
            *(uint4*)&sA[row * SA + c4 * 4] = v;
        }
        // fill B tile: 64 rows x K u32
        for (int idx = tid; idx < 64 * AC4; idx += 256) {
            int row = idx / AC4, c4 = idx % AC4;
            *(uint4*)&sB[row * SA + c4 * 4] = *(const uint4*)&W[(size_t)(n0 + row) * K + c4 * 4];
        }
        __syncthreads();

#pragma unroll
        for (int ks = 0; ks < K / 16; ks++) {
            int kb = ks * 16;
            // A raw packed words: (row, k..k+1) pairs
            uint2 a00 = *(const uint2*)&sA[(mrow    ) * SA + kb + kp];
            uint2 a10 = *(const uint2*)&sA[(mrow + 8) * SA + kb + kp];
            uint2 a01 = *(const uint2*)&sA[(mrow    ) * SA + kb + 8 + kp];
            uint2 a11 = *(const uint2*)&sA[(mrow + 8) * SA + kb + 8 + kp];
            uint32_t ah[4], al[4];
            ah[0] = __byte_perm(a00.x, a00.y, SEL_HI);
            ah[1] = __byte_perm(a10.x, a10.y, SEL_HI);
            ah[2] = __byte_perm(a01.x, a01.y, SEL_HI);
            ah[3] = __byte_perm(a11.x, a11.y, SEL_HI);
            al[0] = __byte_perm(a00.x, a00.y, SEL_LO);
            al[1] = __byte_perm(a10.x, a10.y, SEL_LO);
            al[2] = __byte_perm(a01.x, a01.y, SEL_LO);
            al[3] = __byte_perm(a11.x, a11.y, SEL_LO);
#pragma unroll
            for (int nt = 0; nt < 8; nt++) {
                int nrow = nt * 8 + r;
                uint2 b0 = *(const uint2*)&sB[nrow * SA + kb + kp];
                uint2 b1 = *(const uint2*)&sB[nrow * SA + kb + 8 + kp];
                uint32_t bh0 = __byte_perm(b0.x, b0.y, SEL_HI);
                uint32_t bh1 = __byte_perm(b1.x, b1.y, SEL_HI);
                uint32_t bl0 = __byte_perm(b0.x, b0.y, SEL_LO);
                uint32_t bl1 = __byte_perm(b1.x, b1.y, SEL_LO);
                mma16816(acc[nt], ah, bh0, bh1);   // hi*hi
                mma16816(acc[nt], ah, bl0, bl1);   // hi*lo
                mma16816(acc[nt], al, bh0, bh1);   // lo*hi
            }
        }
    }

    // ---- epilogue ----
    // c0,c1 -> row mrow, cols kp,kp+1 ; c2,c3 -> row mrow+8, same cols
    int row0 = m0 + mrow;
    int row1 = row0 + 8;
#pragma unroll
    for (int nt = 0; nt < 8; nt++) {
        int col = n0 + nt * 8 + kp;
        float bx = bias[col], by = bias[col + 1];
        float v0 = fmaxf(acc[nt][0] + bx, 0.f);
        float v1 = fmaxf(acc[nt][1] + by, 0.f);
        float v2 = fmaxf(acc[nt][2] + bx, 0.f);
        float v3 = fmaxf(acc[nt][3] + by, 0.f);
        if (FINAL) {
            float* o = (float*)outp;
            if (row0 < M) *(float2*)&o[(size_t)row0 * NOUTtot + col] = make_float2(v0, v1);
            if (row1 < M) *(float2*)&o[(size_t)row1 * NOUTtot + col] = make_float2(v2, v3);
        } else {
            uint32_t* o = (uint32_t*)outp;
            if (row0 < M) *(uint2*)&o[(size_t)row0 * NOUTtot + col] = make_uint2(pack_split(v0), pack_split(v1));
            if (row1 < M) *(uint2*)&o[(size_t)row1 * NOUTtot + col] = make_uint2(pack_split(v2), pack_split(v3));
        }
    }
}

// ---------------- launch ----------------
extern "C" void kernel_launch(void* const* d_in, const int* in_sizes, int n_in,
                              void* d_out, int out_size) {
    const float* feat = (const float*)d_in[0];
    const int*   src  = (const int*)d_in[1];
    const int*   dst  = (const int*)d_in[2];
    const float* ew   = (const float*)d_in[3];
    const float* Wp1 = (const float*)d_in[4],  *bp1 = (const float*)d_in[5];
    const float* Ws1 = (const float*)d_in[6],  *Wn1 = (const float*)d_in[7],  *b1 = (const float*)d_in[8];
    const float* Wp2 = (const float*)d_in[9],  *bp2 = (const float*)d_in[10];
    const float* Ws2 = (const float*)d_in[11], *Wn2 = (const float*)d_in[12], *b2 = (const float*)d_in[13];
    const float* Wp3 = (const float*)d_in[14], *bp3 = (const float*)d_in[15];
    const float* Ws3 = (const float*)d_in[16], *Wn3 = (const float*)d_in[17], *b3 = (const float*)d_in[18];
    float* out = (float*)d_out;

    uint32_t *featpk, *hppk, *neighpk, *h1pk, *h2pk, *wpk;
    cudaGetSymbolAddress((void**)&featpk, g_feat_pk);
    cudaGetSymbolAddress((void**)&hppk,   g_hp_pk);
    cudaGetSymbolAddress((void**)&neighpk,g_neigh_pk);
    cudaGetSymbolAddress((void**)&h1pk,   g_h1_pk);
    cudaGetSymbolAddress((void**)&h2pk,   g_h2_pk);
    cudaGetSymbolAddress((void**)&wpk,    g_w_pk);

    const int M = NN;
    const int SM128 = (128 + 64) * (128 + 4) * 4;   // 101376 B
    const int SM64  = (128 + 64) * (64 + 4)  * 4;   // 52224 B
    cudaFuncSetAttribute(mma_gemm<128, false, false>, cudaFuncAttributeMaxDynamicSharedMemorySize, SM128);
    cudaFuncSetAttribute(mma_gemm<128, true,  false>, cudaFuncAttributeMaxDynamicSharedMemorySize, SM128);
    cudaFuncSetAttribute(mma_gemm<128, true,  true >, cudaFuncAttributeMaxDynamicSharedMemorySize, SM128);
    cudaFuncSetAttribute(mma_gemm<64,  false, false>, cudaFuncAttributeMaxDynamicSharedMemorySize, SM64);
    cudaFuncSetAttribute(mma_gemm<64,  true,  false>, cudaFuncAttributeMaxDynamicSharedMemorySize, SM64);

    const int MT = (M + 127) / 128;   // 391 M-tiles

    // ---- pack feat + combined weight prep ----
    pack_feat_kernel<<<(NN * 128 + 255) / 256, 256>>>(feat);
    wprep_all_kernel<<<dim3((128 * 128 + 255) / 256, 9), 256>>>(
        Wp1, Ws1, Wn1, Wp2, Ws2, Wn2, Wp3, Ws3, Wn3);

    // ---- CSR build (dst shared across layers) ----
    zero_counts_kernel<<<(NN + 256) / 256, 256>>>();
    hist_kernel<<<(EE + 255) / 256, 256>>>(dst);
    scan_chunk_kernel<<<NSCAN_BLKS, SCAN_BLK>>>(NN + 1);
    scan_partials_kernel<<<1, 64>>>(NSCAN_BLKS);
    scan_add_kernel<<<NSCAN_BLKS, SCAN_BLK>>>(NN + 1);
    scatter_kernel<<<(EE + 255) / 256, 256>>>(src, dst, ew);

    dim3 nblk((NN * 32 + 255) / 256);

    // ---- Layer 1: 128 -> 64 ----
    mma_gemm<128, false, false><<<dim3(MT, 2), 256, SM128>>>(featpk, wpk + WOFF_P1, nullptr, nullptr, bp1, hppk, M, 128);
    neigh_max_pk<128><<<nblk, 256>>>(hppk, neighpk);
    mma_gemm<128, true,  false><<<dim3(MT, 1), 256, SM128>>>(featpk, wpk + WOFF_S1, neighpk, wpk + WOFF_N1, b1, h1pk, M, 64);

    // ---- Layer 2: 64 -> 128 ----
    mma_gemm<64, false, false><<<dim3(MT, 1), 256, SM64>>>(h1pk, wpk + WOFF_P2, nullptr, nullptr, bp2, hppk, M, 64);
    neigh_max_pk<64><<<nblk, 256>>>(hppk, neighpk);
    mma_gemm<64, true,  false><<<dim3(MT, 2), 256, SM64>>>(h1pk, wpk + WOFF_S2, neighpk, wpk + WOFF_N2, b2, h2pk, M, 128);

    // ---- Layer 3: 128 -> 128 ----
    mma_gemm<128, false, false><<<dim3(MT, 2), 256, SM128>>>(h2pk, wpk + WOFF_P3, nullptr, nullptr, bp3, hppk, M, 128);
    neigh_max_pk<128><<<nblk, 256>>>(hppk, neighpk);
    mma_gemm<128, true,  true ><<<dim3(MT, 2), 256, SM128>>>(h2pk, wpk + WOFF_S3, neighpk, wpk + WOFF_N3, b3, out, M, 128);
}